// round 1
// baseline (speedup 1.0000x reference)
#include <cuda_runtime.h>
#include <cstdint>
#include <cstddef>

#define T_STEPS 4096
#define HD      512
#define NC      4880
#define G3      1536
#define SCAN_CTAS 64

// ---------------- scratch (static device globals; no allocation) ----------------
__device__ float g_visit[(size_t)T_STEPS * HD];     // 8 MB
__device__ float g_gi[(size_t)T_STEPS * G3];        // 25 MB
__device__ float g_hs[(size_t)T_STEPS * HD];        // 8 MB
__device__ float g_logits[T_STEPS];
__device__ float g_alpha[T_STEPS];
__device__ int   g_flags[T_STEPS];

// ---------------- generic fp32 SIMT GEMM: C[M,N] = A x B (+bias) ----------------
// A_KMAJ: A stored [K, M] (element A[k*lda + m]); else [M, K] (A[m*lda + k])
// B_KMAJ: B stored [K, N] (element B[k*ldb + n]); else [N, K] (B[n*ldb + k])
// BM=128, BN=64, BK=16, 256 threads, 8x4 per thread.
template <bool A_KMAJ, bool B_KMAJ, bool BIAS>
__global__ __launch_bounds__(256)
void gemm_kernel(const float* __restrict__ A, const float* __restrict__ B,
                 const float* __restrict__ bias, float* __restrict__ C,
                 int M, int N, int K, int lda, int ldb, int ldc)
{
    constexpr int BM = 128, BN = 64, BK = 16;
    __shared__ float As[BK][BM + 4];
    __shared__ float Bs[BK][BN + 4];

    const int tid = threadIdx.x;
    const int tx  = tid & 15;   // n
    const int ty  = tid >> 4;   // m
    const int m0  = blockIdx.y * BM;
    const int n0  = blockIdx.x * BN;

    float acc[8][4];
#pragma unroll
    for (int i = 0; i < 8; i++)
#pragma unroll
        for (int j = 0; j < 4; j++) acc[i][j] = 0.f;

    for (int k0 = 0; k0 < K; k0 += BK) {
        // ---- load A tile: BK x BM = 512 float4 ----
        if (A_KMAJ) {
#pragma unroll
            for (int it = 0; it < 2; it++) {
                int idx = tid + it * 256;          // 0..511
                int kk  = idx >> 5;                // /32
                int mm4 = idx & 31;
                float4 v = *(const float4*)&A[(size_t)(k0 + kk) * lda + m0 + mm4 * 4];
                *(float4*)&As[kk][mm4 * 4] = v;
            }
        } else {
#pragma unroll
            for (int it = 0; it < 2; it++) {
                int idx = tid + it * 256;
                int mm  = idx >> 2;                // 0..127
                int k4  = idx & 3;
                float4 v = *(const float4*)&A[(size_t)(m0 + mm) * lda + k0 + k4 * 4];
                As[k4 * 4 + 0][mm] = v.x;
                As[k4 * 4 + 1][mm] = v.y;
                As[k4 * 4 + 2][mm] = v.z;
                As[k4 * 4 + 3][mm] = v.w;
            }
        }
        // ---- load B tile: BK x BN = 256 float4 ----
        if (B_KMAJ) {
            int kk  = tid >> 4;
            int nn4 = tid & 15;
            float4 v = *(const float4*)&B[(size_t)(k0 + kk) * ldb + n0 + nn4 * 4];
            *(float4*)&Bs[kk][nn4 * 4] = v;
        } else {
            int nn = tid >> 2;
            int k4 = tid & 3;
            float4 v = *(const float4*)&B[(size_t)(nn + n0) * ldb + k0 + k4 * 4];
            Bs[k4 * 4 + 0][nn] = v.x;
            Bs[k4 * 4 + 1][nn] = v.y;
            Bs[k4 * 4 + 2][nn] = v.z;
            Bs[k4 * 4 + 3][nn] = v.w;
        }
        __syncthreads();

#pragma unroll
        for (int kk = 0; kk < BK; kk++) {
            float4 a0 = *(const float4*)&As[kk][ty * 8];
            float4 a1 = *(const float4*)&As[kk][ty * 8 + 4];
            float4 b0 = *(const float4*)&Bs[kk][tx * 4];
            float a[8] = {a0.x, a0.y, a0.z, a0.w, a1.x, a1.y, a1.z, a1.w};
            float b[4] = {b0.x, b0.y, b0.z, b0.w};
#pragma unroll
            for (int i = 0; i < 8; i++)
#pragma unroll
                for (int j = 0; j < 4; j++) acc[i][j] += a[i] * b[j];
        }
        __syncthreads();
    }

    float4 bv = make_float4(0.f, 0.f, 0.f, 0.f);
    if (BIAS) bv = *(const float4*)&bias[n0 + tx * 4];
#pragma unroll
    for (int i = 0; i < 8; i++) {
        int m = m0 + ty * 8 + i;
        float4 v;
        v.x = acc[i][0] + bv.x;
        v.y = acc[i][1] + bv.y;
        v.z = acc[i][2] + bv.z;
        v.w = acc[i][3] + bv.w;
        *(float4*)&C[(size_t)m * ldc + n0 + tx * 4] = v;
    }
}

// ---------------- zero flags ----------------
__global__ void zero_flags_kernel()
{
    int i = blockIdx.x * blockDim.x + threadIdx.x;
    if (i < T_STEPS) g_flags[i] = 0;
}

// ---------------- GRU scan: 64 CTAs x 256 threads, global flag sync ----------------
// CTA c owns hidden indices [8c, 8c+8); warp w handles index j = 8c + w.
// SMEM: Ws[8 warps][3 gates][512] = 48KB, then h_s[512].
__global__ __launch_bounds__(256)
void gru_scan_kernel(const float* __restrict__ W_hh, const float* __restrict__ b_hh)
{
    extern __shared__ float sm[];
    float* Ws  = sm;                 // 8*3*512
    float* h_s = sm + 8 * 3 * 512;   // 512

    const int tid  = threadIdx.x;
    const int w    = tid >> 5;
    const int lane = tid & 31;
    const int jglob = blockIdx.x * 8 + w;

    // load this CTA's 24 W_hh rows into SMEM (once)
    for (int idx = tid; idx < 8 * 3 * 512; idx += 256) {
        int ww  = idx / 1536;
        int rem = idx - ww * 1536;
        int g   = rem >> 9;
        int k   = rem & 511;
        Ws[idx] = W_hh[(size_t)(g * HD + blockIdx.x * 8 + ww) * HD + k];
    }
    float bhr = 0.f, bhz = 0.f, bhn = 0.f;
    if (lane == 0) {
        bhr = b_hh[jglob];
        bhz = b_hh[HD + jglob];
        bhn = b_hh[2 * HD + jglob];
    }
    h_s[tid] = 0.f;
    h_s[tid + 256] = 0.f;
    __syncthreads();

    const float* wr = Ws + (w * 3 + 0) * 512;
    const float* wz = Ws + (w * 3 + 1) * 512;
    const float* wn = Ws + (w * 3 + 2) * 512;
    const int base = lane * 16;

    for (int t = 0; t < T_STEPS; t++) {
        // prefetch gi values for this step (independent of h)
        float gr = 0.f, gz = 0.f, gn = 0.f;
        if (lane == 0) {
            const float* gt = g_gi + (size_t)t * G3;
            gr = gt[jglob];
            gz = gt[HD + jglob];
            gn = gt[2 * HD + jglob];
        }

        if (t > 0) {
            if (tid == 0) {
                int v;
                do {
                    asm volatile("ld.acquire.gpu.global.s32 %0, [%1];"
                                 : "=r"(v) : "l"(g_flags + t - 1) : "memory");
                } while (v < SCAN_CTAS);
            }
            __syncthreads();
            const float* hp = g_hs + (size_t)(t - 1) * HD;
            h_s[tid]       = hp[tid];
            h_s[tid + 256] = hp[tid + 256];
            __syncthreads();
        }

        // three dots of length 512 for this warp's index
        float accr = 0.f, accz = 0.f, accn = 0.f;
#pragma unroll
        for (int i = 0; i < 16; i += 4) {
            float4 hv  = *(const float4*)&h_s[base + i];
            float4 wrv = *(const float4*)&wr[base + i];
            float4 wzv = *(const float4*)&wz[base + i];
            float4 wnv = *(const float4*)&wn[base + i];
            accr += hv.x * wrv.x + hv.y * wrv.y + hv.z * wrv.z + hv.w * wrv.w;
            accz += hv.x * wzv.x + hv.y * wzv.y + hv.z * wzv.z + hv.w * wzv.w;
            accn += hv.x * wnv.x + hv.y * wnv.y + hv.z * wnv.z + hv.w * wnv.w;
        }
#pragma unroll
        for (int off = 16; off > 0; off >>= 1) {
            accr += __shfl_down_sync(0xffffffffu, accr, off);
            accz += __shfl_down_sync(0xffffffffu, accz, off);
            accn += __shfl_down_sync(0xffffffffu, accn, off);
        }

        if (lane == 0) {
            float r  = 1.f / (1.f + __expf(-(gr + accr + bhr)));
            float z  = 1.f / (1.f + __expf(-(gz + accz + bhz)));
            float nv = tanhf(gn + r * (accn + bhn));
            float hn = (1.f - z) * nv + z * h_s[jglob];
            g_hs[(size_t)t * HD + jglob] = hn;
            __threadfence();
        }
        __syncthreads();
        if (tid == 0) {
            __threadfence();
            atomicAdd(g_flags + t, 1);
        }
    }
}

// ---------------- logits[t] = dot(hs[t], w_att) ----------------
__global__ __launch_bounds__(256)
void logits_kernel(const float* __restrict__ w_att)
{
    __shared__ float watt[HD];
    const int tid  = threadIdx.x;
    const int w    = tid >> 5;
    const int lane = tid & 31;
    watt[tid]       = w_att[tid];
    watt[tid + 256] = w_att[tid + 256];
    __syncthreads();

    int t = blockIdx.x * 8 + w;
    const float* h = g_hs + (size_t)t * HD;
    float acc = 0.f;
    int base = lane * 16;
#pragma unroll
    for (int i = 0; i < 16; i += 4) {
        float4 hv = *(const float4*)&h[base + i];
        float4 wv = *(const float4*)&watt[base + i];
        acc += hv.x * wv.x + hv.y * wv.y + hv.z * wv.z + hv.w * wv.w;
    }
#pragma unroll
    for (int off = 16; off > 0; off >>= 1)
        acc += __shfl_down_sync(0xffffffffu, acc, off);
    if (lane == 0) g_logits[t] = acc;
}

// ---------------- softmax over 4096 logits; also zero d_out ----------------
__global__ __launch_bounds__(1024)
void softmax_kernel(float* __restrict__ out)
{
    __shared__ float red[32];
    const int tid  = threadIdx.x;
    const int lane = tid & 31;
    const int wrp  = tid >> 5;

    float m = -1e30f;
    for (int i = tid; i < T_STEPS; i += 1024) m = fmaxf(m, g_logits[i]);
#pragma unroll
    for (int o = 16; o > 0; o >>= 1) m = fmaxf(m, __shfl_xor_sync(0xffffffffu, m, o));
    if (lane == 0) red[wrp] = m;
    __syncthreads();
    if (wrp == 0) {
        float v = red[lane];
#pragma unroll
        for (int o = 16; o > 0; o >>= 1) v = fmaxf(v, __shfl_xor_sync(0xffffffffu, v, o));
        if (lane == 0) red[0] = v;
    }
    __syncthreads();
    m = red[0];
    __syncthreads();

    float s = 0.f;
    for (int i = tid; i < T_STEPS; i += 1024) {
        float e = __expf(g_logits[i] - m);
        g_alpha[i] = e;
        s += e;
    }
#pragma unroll
    for (int o = 16; o > 0; o >>= 1) s += __shfl_xor_sync(0xffffffffu, s, o);
    if (lane == 0) red[wrp] = s;
    __syncthreads();
    if (wrp == 0) {
        float v = red[lane];
#pragma unroll
        for (int o = 16; o > 0; o >>= 1) v += __shfl_xor_sync(0xffffffffu, v, o);
        if (lane == 0) red[0] = v;
    }
    __syncthreads();
    float inv = 1.f / red[0];
    for (int i = tid; i < T_STEPS; i += 1024) g_alpha[i] *= inv;

    if (tid < HD) out[tid] = 0.f;
}

// ---------------- out[d] += sum_t alpha[t] * hs[t][d] ----------------
__global__ __launch_bounds__(256)
void wsum_kernel(float* __restrict__ out)
{
    const int tid = threadIdx.x;
    const int d   = tid * 2;
    float ax = 0.f, ay = 0.f;
    int t0 = blockIdx.x * 64;
#pragma unroll 4
    for (int tt = 0; tt < 64; tt++) {
        int t = t0 + tt;
        float a = g_alpha[t];
        float2 hv = *(const float2*)&g_hs[(size_t)t * HD + d];
        ax += a * hv.x;
        ay += a * hv.y;
    }
    atomicAdd(out + d, ax);
    atomicAdd(out + d + 1, ay);
}

// ---------------- launcher ----------------
extern "C" void kernel_launch(void* const* d_in, const int* in_sizes, int n_in,
                              void* d_out, int out_size)
{
    const float* H     = (const float*)d_in[0];
    // d_in[1] = TE (unused)
    const float* X_emb = (const float*)d_in[2];
    const float* W_ih  = (const float*)d_in[3];
    const float* W_hh  = (const float*)d_in[4];
    const float* b_ih  = (const float*)d_in[5];
    const float* b_hh  = (const float*)d_in[6];
    const float* w_att = (const float*)d_in[7];
    float* out = (float*)d_out;

    float* visit; float* gi;
    cudaGetSymbolAddress((void**)&visit, g_visit);
    cudaGetSymbolAddress((void**)&gi, g_gi);

    const int scan_smem = (8 * 3 * 512 + 512) * (int)sizeof(float);  // 51200 B
    cudaFuncSetAttribute(gru_scan_kernel,
                         cudaFuncAttributeMaxDynamicSharedMemorySize, scan_smem);

    // 1) visit_emb[4096,512] = H^T @ X_emb   (A: K-major 4880x4096, B: K-major 4880x512)
    {
        dim3 grid(HD / 64, T_STEPS / 128);
        gemm_kernel<true, true, false><<<grid, 256>>>(
            H, X_emb, nullptr, visit, T_STEPS, HD, NC, T_STEPS, HD, HD);
    }
    // 2) gi[4096,1536] = visit_emb @ W_ih^T + b_ih  (A: M-major, B: N-major)
    {
        dim3 grid(G3 / 64, T_STEPS / 128);
        gemm_kernel<false, false, true><<<grid, 256>>>(
            visit, W_ih, b_ih, gi, T_STEPS, G3, HD, HD, HD, G3);
    }
    // 3) reset sync flags
    zero_flags_kernel<<<T_STEPS / 256, 256>>>();
    // 4) sequential GRU scan
    gru_scan_kernel<<<SCAN_CTAS, 256, scan_smem>>>(W_hh, b_hh);
    // 5) attention logits
    logits_kernel<<<T_STEPS / 8, 256>>>(w_att);
    // 6) softmax (+ zero out)
    softmax_kernel<<<1, 1024>>>(out);
    // 7) weighted sum
    wsum_kernel<<<T_STEPS / 64, 256>>>(out);
}